// round 9
// baseline (speedup 1.0000x reference)
#include <cuda_runtime.h>
#include <cstdint>

// Problem constants
#define B_  16
#define H_  224
#define W_  224
#define C_  96
#define TW  32          // output pixels per block (one row segment)
#define NT  256         // threads per block
#define INW (TW + 2)    // 34 input cols incl. halo
#define WTP 100         // sWt pitch (floats): co*100+ci, 16B-aligned rows
#define DWP 100         // sDw pitch (floats): pg*100 spans 8 bank groups (2-way max)

// Shared-memory layout (in floats)
//   sWt : 96*100     = 9600   (TRANSPOSED pointwise weights: [co][ci])
//   sIn : 3*34*96    = 9792   (ReLU'd input tile with halo, zero-padded)
//   sDw : 32*100     = 3200   (depthwise results, [pixel][ci])
//   sKw : 3*3*96     = 864    (depthwise weights)
//   sSc : 96                   (BN scale = gamma*rsqrt(var+eps))
//   sSh : 96                   (BN shift = beta - mean*scale + pw_bias*scale)
//   sDb : 96                   (depthwise bias)
#define OFF_WT  0
#define OFF_IN  9600
#define OFF_DW  (9600 + 9792)
#define OFF_KW  (9600 + 9792 + 3200)
#define OFF_SC  (9600 + 9792 + 3200 + 864)
#define OFF_SH  (OFF_SC + 96)
#define OFF_DB  (OFF_SC + 192)
#define SMEM_FLOATS (9600 + 9792 + 3200 + 864 + 288)      // 23744
#define SMEM_BYTES  (SMEM_FLOATS * 4)                     // 94976  -> 2 blocks/SM

typedef unsigned long long ull;

__device__ __forceinline__ ull pack2(float lo, float hi) {
    ull r;
    asm("mov.b64 %0, {%1, %2};" : "=l"(r) : "f"(lo), "f"(hi));
    return r;
}
__device__ __forceinline__ void ffma2(ull& d, ull a, ull b) {
    // d = a * b + d  (packed f32x2 — 2x FFMA throughput, PTX-only pattern)
    asm("fma.rn.f32x2 %0, %1, %2, %0;" : "+l"(d) : "l"(a), "l"(b));
}
__device__ __forceinline__ void unpack2(ull v, float& lo, float& hi) {
    asm("mov.b64 {%0, %1}, %2;" : "=f"(lo), "=f"(hi) : "l"(v));
}

__global__ void __launch_bounds__(NT, 2)
sepconv_kernel(const float* __restrict__ x,
               const float* __restrict__ dwk,    // (3,3,1,96)
               const float* __restrict__ dwb,    // (96)
               const float* __restrict__ pwk,    // (1,1,96,96) [ci][co]
               const float* __restrict__ pwb,    // (96)
               const float* __restrict__ gamma,
               const float* __restrict__ beta,
               const float* __restrict__ mmean,
               const float* __restrict__ mvar,
               float* __restrict__ out)
{
    extern __shared__ float sm[];
    float* sWt = sm + OFF_WT;
    float* sIn = sm + OFF_IN;
    float* sDw = sm + OFF_DW;
    float* sKw = sm + OFF_KW;
    float* sSc = sm + OFF_SC;
    float* sSh = sm + OFF_SH;
    float* sDb = sm + OFF_DB;

    const int tid = threadIdx.x;
    const int w0  = blockIdx.x * TW;
    const int h   = blockIdx.y;
    const int b   = blockIdx.z;

    // ---- Phase 1: stage weights / BN params / input tile -------------------
    {   // pointwise weights, transposed into sWt[co][ci]
        const float4* src = (const float4*)pwk;   // layout [ci][co/4]
        #pragma unroll
        for (int i = tid; i < (C_ * C_) / 4; i += NT) {
            float4 v = src[i];
            int ci = i / (C_ / 4);
            int co = (i % (C_ / 4)) * 4;
            sWt[(co + 0) * WTP + ci] = v.x;
            sWt[(co + 1) * WTP + ci] = v.y;
            sWt[(co + 2) * WTP + ci] = v.z;
            sWt[(co + 3) * WTP + ci] = v.w;
        }
    }
    for (int i = tid; i < 9 * C_; i += NT) sKw[i] = dwk[i];
    if (tid < C_) {
        float inv = gamma[tid] * rsqrtf(mvar[tid] + 1e-3f);
        sSc[tid] = inv;
        sSh[tid] = beta[tid] - mmean[tid] * inv + pwb[tid] * inv;
        sDb[tid] = dwb[tid];
    }
    {   // input tile with halo: 3 rows x 34 cols x 96 ch, ReLU'd, zero-padded
        const int NQ = C_ / 4;               // 24 float4 per pixel
        for (int i = tid; i < 3 * INW * NQ; i += NT) {
            int pix = i / NQ;
            int q   = i - pix * NQ;
            int r   = pix / INW;
            int col = pix - r * INW;
            int gh  = h - 1 + r;
            int gw  = w0 - 1 + col;
            float4 v = make_float4(0.f, 0.f, 0.f, 0.f);
            if ((unsigned)gh < (unsigned)H_ && (unsigned)gw < (unsigned)W_) {
                v = *(const float4*)(x + (((size_t)b * H_ + gh) * W_ + gw) * C_ + q * 4);
                v.x = fmaxf(v.x, 0.f); v.y = fmaxf(v.y, 0.f);
                v.z = fmaxf(v.z, 0.f); v.w = fmaxf(v.w, 0.f);
            }
            *(float4*)(sIn + pix * C_ + q * 4) = v;
        }
    }
    __syncthreads();

    // ---- Phase 2: depthwise 3x3 -> sDw[p][c], float4-vectorized ------------
    // 32 pixels x 24 channel-quads = 768 items; 3 per thread
    #pragma unroll
    for (int i = 0; i < 3; i++) {
        int idx = tid + i * NT;
        int q = idx % 24;             // channel quad
        int p = idx / 24;             // pixel
        ulonglong2 acc = *(const ulonglong2*)(sDb + q * 4);
        #pragma unroll
        for (int r = 0; r < 3; r++) {
            #pragma unroll
            for (int s = 0; s < 3; s++) {
                ulonglong2 in = *(const ulonglong2*)(sIn + (r * INW + p + s) * C_ + q * 4);
                ulonglong2 kk = *(const ulonglong2*)(sKw + (r * 3 + s) * C_ + q * 4);
                ffma2(acc.x, in.x, kk.x);
                ffma2(acc.y, in.y, kk.y);
            }
        }
        *(ulonglong2*)(sDw + p * DWP + q * 4) = acc;
    }
    __syncthreads();

    // ---- Phase 3: pointwise 96x96 GEMM (packed-lane f32x2) + BN + store ----
    // thread -> pixels {pg, pg+16} x 6 output channels (cg*6 .. cg*6+5)
    // accumulate over k in packed lanes: acc = (sum_even_k, sum_odd_k); hadd at end
    const int pg = tid & 15;
    const int cg = tid >> 4;
    const int p0 = pg;
    const int p1 = pg + 16;
    const int cb = cg * 6;

    ull acc0[6] = {0, 0, 0, 0, 0, 0};
    ull acc1[6] = {0, 0, 0, 0, 0, 0};

    const float* a0p = sDw + p0 * DWP;
    const float* a1p = sDw + p1 * DWP;

    #pragma unroll 4
    for (int kc = 0; kc < C_; kc += 4) {
        ulonglong2 a0 = *(const ulonglong2*)(a0p + kc);
        ulonglong2 a1 = *(const ulonglong2*)(a1p + kc);
        #pragma unroll
        for (int j = 0; j < 6; j++) {
            ulonglong2 w = *(const ulonglong2*)(sWt + (cb + j) * WTP + kc);
            ffma2(acc0[j], a0.x, w.x);
            ffma2(acc0[j], a0.y, w.y);
            ffma2(acc1[j], a1.x, w.x);
            ffma2(acc1[j], a1.y, w.y);
        }
    }

    // Epilogue: horizontal add, BN, store
    float sc[6], sh[6];
    #pragma unroll
    for (int j = 0; j < 6; j++) { sc[j] = sSc[cb + j]; sh[j] = sSh[cb + j]; }

    float* op0 = out + (((size_t)b * H_ + h) * W_ + (w0 + p0)) * C_ + cb;
    float* op1 = out + (((size_t)b * H_ + h) * W_ + (w0 + p1)) * C_ + cb;

    float r0[6], r1[6];
    #pragma unroll
    for (int j = 0; j < 6; j++) {
        float lo, hi;
        unpack2(acc0[j], lo, hi);
        r0[j] = fmaf(lo + hi, sc[j], sh[j]);
        unpack2(acc1[j], lo, hi);
        r1[j] = fmaf(lo + hi, sc[j], sh[j]);
    }
    *(ull*)(op0)     = pack2(r0[0], r0[1]);
    *(ull*)(op0 + 2) = pack2(r0[2], r0[3]);
    *(ull*)(op0 + 4) = pack2(r0[4], r0[5]);
    *(ull*)(op1)     = pack2(r1[0], r1[1]);
    *(ull*)(op1 + 2) = pack2(r1[2], r1[3]);
    *(ull*)(op1 + 4) = pack2(r1[4], r1[5]);
}

extern "C" void kernel_launch(void* const* d_in, const int* in_sizes, int n_in,
                              void* d_out, int out_size)
{
    (void)in_sizes; (void)n_in; (void)out_size;
    const float* x     = (const float*)d_in[0];
    const float* dwk   = (const float*)d_in[1];
    const float* dwb   = (const float*)d_in[2];
    const float* pwk   = (const float*)d_in[3];
    const float* pwb   = (const float*)d_in[4];
    const float* gamma = (const float*)d_in[5];
    const float* beta  = (const float*)d_in[6];
    const float* mmean = (const float*)d_in[7];
    const float* mvar  = (const float*)d_in[8];
    float* out = (float*)d_out;

    cudaFuncSetAttribute(sepconv_kernel,
                         cudaFuncAttributeMaxDynamicSharedMemorySize, SMEM_BYTES);

    dim3 grid(W_ / TW, H_, B_);
    sepconv_kernel<<<grid, NT, SMEM_BYTES>>>(
        x, dwk, dwb, pwk, pwb, gamma, beta, mmean, mvar, out);
}

// round 11
// speedup vs baseline: 1.3612x; 1.3612x over previous
#include <cuda_runtime.h>
#include <cuda_bf16.h>
#include <cstdint>

// ---------------- problem constants ----------------
#define B_   16
#define H_   224
#define W_   224
#define C_   96
#define TPX  112          // pixels owned per block
#define M_   128          // GEMM M tile (rows 112..127 are scratch)
#define NT   256          // 8 warps
#define PW   52           // smem row pitch in 32-bit words (=104 bf16)

// ---------------- smem layout (uint32 words) ----------------
#define O_AHI 0                         // A hi: 128 x 52 words
#define O_ALO (128 * PW)                // A lo
#define O_WHI (2 * 128 * PW)            // W hi: 96 x 52 words
#define O_WLO (2 * 128 * PW + 96 * PW)  // W lo
#define O_KW  (2 * 128 * PW + 2 * 96 * PW)   // dw weights 9*96 f32
#define O_SC  (O_KW + 9 * 96)
#define O_SH  (O_SC + 96)
#define O_DB  (O_SH + 96)
#define SMEM_WORDS (O_DB + 96)          // 24448
#define SMEM_BYTES (SMEM_WORDS * 4)     // 97792

// bf16 mma.sync m16n8k16 (legacy tensor path — compiles on compute_103 base)
__device__ __forceinline__ void mma16816(float* d,
    uint32_t a0, uint32_t a1, uint32_t a2, uint32_t a3,
    uint32_t b0, uint32_t b1)
{
    asm volatile(
        "mma.sync.aligned.m16n8k16.row.col.f32.bf16.bf16.f32 "
        "{%0,%1,%2,%3}, {%4,%5,%6,%7}, {%8,%9}, {%0,%1,%2,%3};"
        : "+f"(d[0]), "+f"(d[1]), "+f"(d[2]), "+f"(d[3])
        : "r"(a0), "r"(a1), "r"(a2), "r"(a3), "r"(b0), "r"(b1));
}

__device__ __forceinline__ uint32_t pack_bf2(float lo, float hi) {
    __nv_bfloat162 v = __floats2bfloat162_rn(lo, hi);   // .x = lo lane
    return *(uint32_t*)&v;
}

__global__ void __launch_bounds__(NT, 2)
sepconv_mma_kernel(const float* __restrict__ x,
                   const float* __restrict__ dwk,    // (3,3,1,96)
                   const float* __restrict__ dwb,    // (96)
                   const float* __restrict__ pwk,    // (1,1,96,96) [ci][co]
                   const float* __restrict__ pwb,    // (96)
                   const float* __restrict__ gamma,
                   const float* __restrict__ beta,
                   const float* __restrict__ mmean,
                   const float* __restrict__ mvar,
                   float* __restrict__ out)
{
    extern __shared__ uint32_t sm[];
    uint32_t* sAhi = sm + O_AHI;
    uint32_t* sAlo = sm + O_ALO;
    uint32_t* sWhi = sm + O_WHI;
    uint32_t* sWlo = sm + O_WLO;
    float* sKw = (float*)(sm + O_KW);
    float* sSc = (float*)(sm + O_SC);
    float* sSh = (float*)(sm + O_SH);
    float* sDb = (float*)(sm + O_DB);

    const int tid = threadIdx.x;
    const int wid = tid >> 5;
    const int l   = tid & 31;
    const int w0  = blockIdx.x * TPX;
    const int h   = blockIdx.y;
    const int b   = blockIdx.z;

    // ---- Phase 0: stage pointwise W (bf16 hi/lo, [co][ci]), dw weights, BN --
    // W: iterate (co, ci-word); pwk is [ci][co]
    for (int i = tid; i < C_ * (C_ / 2); i += NT) {
        int co = i / (C_ / 2);
        int cw = i - co * (C_ / 2);          // ci word (2 channels)
        float w0f = pwk[(2 * cw) * C_ + co];
        float w1f = pwk[(2 * cw + 1) * C_ + co];
        float h0 = __bfloat162float(__float2bfloat16_rn(w0f));
        float h1 = __bfloat162float(__float2bfloat16_rn(w1f));
        sWhi[co * PW + cw] = pack_bf2(h0, h1);
        sWlo[co * PW + cw] = pack_bf2(w0f - h0, w1f - h1);
    }
    for (int i = tid; i < 9 * C_; i += NT) sKw[i] = dwk[i];
    if (tid < C_) {
        float inv = gamma[tid] * rsqrtf(mvar[tid] + 1e-3f);
        sSc[tid] = inv;
        sSh[tid] = beta[tid] - mmean[tid] * inv + pwb[tid] * inv;
        sDb[tid] = dwb[tid];
    }
    __syncthreads();

    // ---- Phase A: depthwise fp32 (2 threads/pixel x 48 ch) -> bf16 hi/lo smem
    {
        const int p   = tid >> 1;            // pixel row in tile (0..127)
        const int ch0 = (tid & 1) * 48;      // channel base
        const int w   = w0 + p;

        float acc[48];
        #pragma unroll
        for (int q = 0; q < 12; q++) {
            float4 bv = *(const float4*)(sDb + ch0 + q * 4);
            acc[q*4+0] = bv.x; acc[q*4+1] = bv.y;
            acc[q*4+2] = bv.z; acc[q*4+3] = bv.w;
        }
        #pragma unroll
        for (int nb = 0; nb < 9; nb++) {
            const int dh = nb / 3 - 1;
            const int dx = nb % 3 - 1;
            const int hh = h + dh;
            const int ww = w + dx;
            const bool v = ((unsigned)hh < (unsigned)H_) && ((unsigned)ww < (unsigned)W_);
            const float4* px = (const float4*)(x + (((size_t)b * H_ + hh) * W_ + ww) * C_ + ch0);
            const float4* kw = (const float4*)(sKw + nb * C_ + ch0);
            #pragma unroll
            for (int q = 0; q < 12; q++) {
                float4 xv = v ? __ldg(px + q) : make_float4(0.f, 0.f, 0.f, 0.f);
                float4 kv = kw[q];
                acc[q*4+0] = fmaf(fmaxf(xv.x, 0.f), kv.x, acc[q*4+0]);
                acc[q*4+1] = fmaf(fmaxf(xv.y, 0.f), kv.y, acc[q*4+1]);
                acc[q*4+2] = fmaf(fmaxf(xv.z, 0.f), kv.z, acc[q*4+2]);
                acc[q*4+3] = fmaf(fmaxf(xv.w, 0.f), kv.w, acc[q*4+3]);
            }
        }
        // split to bf16 hi/lo and store (word = 2 channels)
        const int wbase = p * PW + ch0 / 2;
        #pragma unroll
        for (int c = 0; c < 24; c += 2) {
            float a0 = acc[2*c],   a1 = acc[2*c+1];
            float a2 = acc[2*c+2], a3 = acc[2*c+3];
            float h0 = __bfloat162float(__float2bfloat16_rn(a0));
            float h1 = __bfloat162float(__float2bfloat16_rn(a1));
            float h2 = __bfloat162float(__float2bfloat16_rn(a2));
            float h3 = __bfloat162float(__float2bfloat16_rn(a3));
            uint2 hi = make_uint2(pack_bf2(h0, h1), pack_bf2(h2, h3));
            uint2 lo = make_uint2(pack_bf2(a0 - h0, a1 - h1), pack_bf2(a2 - h2, a3 - h3));
            *(uint2*)(sAhi + wbase + c) = hi;
            *(uint2*)(sAlo + wbase + c) = lo;
        }
    }
    __syncthreads();

    // ---- Phase B: GEMM M=128 N=96 K=96, bf16 split (hi*hi + hi*lo + lo*hi) --
    // warp wid owns rows m0..m0+15; lane l: groupID = l/4, tg = l%4
    const int m0 = wid * 16;
    const int g  = l >> 2;
    const int tg = l & 3;

    float d[12][4];
    #pragma unroll
    for (int j = 0; j < 12; j++) {
        d[j][0] = 0.f; d[j][1] = 0.f; d[j][2] = 0.f; d[j][3] = 0.f;
    }

    #pragma unroll
    for (int k = 0; k < 6; k++) {          // k0 = k*16, word base k*8
        const int aw = (m0 + g) * PW + k * 8 + tg;
        const uint32_t ah0 = sAhi[aw];
        const uint32_t ah1 = sAhi[aw + 8 * PW];
        const uint32_t ah2 = sAhi[aw + 4];
        const uint32_t ah3 = sAhi[aw + 8 * PW + 4];
        const uint32_t al0 = sAlo[aw];
        const uint32_t al1 = sAlo[aw + 8 * PW];
        const uint32_t al2 = sAlo[aw + 4];
        const uint32_t al3 = sAlo[aw + 8 * PW + 4];
        #pragma unroll
        for (int j = 0; j < 12; j++) {
            const int bw = (j * 8 + g) * PW + k * 8 + tg;
            const uint32_t bh0 = sWhi[bw];
            const uint32_t bh1 = sWhi[bw + 4];
            const uint32_t bl0 = sWlo[bw];
            const uint32_t bl1 = sWlo[bw + 4];
            mma16816(d[j], ah0, ah1, ah2, ah3, bh0, bh1);
            mma16816(d[j], ah0, ah1, ah2, ah3, bl0, bl1);
            mma16816(d[j], al0, al1, al2, al3, bh0, bh1);
        }
    }

    // ---- Epilogue: BN + store (rows 0..111 only -> warps 0..6) -------------
    if (wid < 7) {
        const int r0 = m0 + g;
        float* base0 = out + (((size_t)b * H_ + h) * W_ + (w0 + r0)) * C_;
        float* base1 = base0 + 8 * (size_t)C_;
        #pragma unroll
        for (int j = 0; j < 12; j++) {
            const int col = j * 8 + tg * 2;
            float2 sc = *(const float2*)(sSc + col);
            float2 sh = *(const float2*)(sSh + col);
            float2 r;
            r.x = fmaf(d[j][0], sc.x, sh.x);
            r.y = fmaf(d[j][1], sc.y, sh.y);
            *(float2*)(base0 + col) = r;
            r.x = fmaf(d[j][2], sc.x, sh.x);
            r.y = fmaf(d[j][3], sc.y, sh.y);
            *(float2*)(base1 + col) = r;
        }
    }
}

extern "C" void kernel_launch(void* const* d_in, const int* in_sizes, int n_in,
                              void* d_out, int out_size)
{
    (void)in_sizes; (void)n_in; (void)out_size;
    const float* x     = (const float*)d_in[0];
    const float* dwk   = (const float*)d_in[1];
    const float* dwb   = (const float*)d_in[2];
    const float* pwk   = (const float*)d_in[3];
    const float* pwb   = (const float*)d_in[4];
    const float* gamma = (const float*)d_in[5];
    const float* beta  = (const float*)d_in[6];
    const float* mmean = (const float*)d_in[7];
    const float* mvar  = (const float*)d_in[8];
    float* out = (float*)d_out;

    cudaFuncSetAttribute(sepconv_mma_kernel,
                         cudaFuncAttributeMaxDynamicSharedMemorySize, SMEM_BYTES);

    dim3 grid(W_ / TPX, H_, B_);           // (2, 224, 16)
    sepconv_mma_kernel<<<grid, NT, SMEM_BYTES>>>(
        x, dwk, dwb, pwk, pwb, gamma, beta, mmean, mvar, out);
}

// round 12
// speedup vs baseline: 2.1913x; 1.6099x over previous
#include <cuda_runtime.h>
#include <cuda_bf16.h>
#include <cstdint>

// ---------------- problem constants ----------------
#define B_   16
#define H_   224
#define W_   224
#define C_   96
#define TPX  112          // pixels owned per block
#define NT   256          // 8 warps
#define PW   52           // smem row pitch in 32-bit words (=104 bf16)

// ---------------- smem layout (uint32 words) ----------------
#define O_AHI 0                         // A hi: 128 x 52 words
#define O_ALO (128 * PW)                // A lo
#define O_WHI (2 * 128 * PW)            // W hi: 96 x 52 words
#define O_WLO (2 * 128 * PW + 96 * PW)  // W lo
#define O_KW  (2 * 128 * PW + 2 * 96 * PW)   // dw weights 9*96 f32 (nb-major)
#define O_SC  (O_KW + 9 * 96)
#define O_SH  (O_SC + 96)
#define O_DB  (O_SH + 96)
#define SMEM_WORDS (O_DB + 96)          // 24448
#define SMEM_BYTES (SMEM_WORDS * 4)     // 97792

// bf16 mma.sync m16n8k16 (legacy tensor path — compiles on compute_103 base)
__device__ __forceinline__ void mma16816(float* d,
    uint32_t a0, uint32_t a1, uint32_t a2, uint32_t a3,
    uint32_t b0, uint32_t b1)
{
    asm volatile(
        "mma.sync.aligned.m16n8k16.row.col.f32.bf16.bf16.f32 "
        "{%0,%1,%2,%3}, {%4,%5,%6,%7}, {%8,%9}, {%0,%1,%2,%3};"
        : "+f"(d[0]), "+f"(d[1]), "+f"(d[2]), "+f"(d[3])
        : "r"(a0), "r"(a1), "r"(a2), "r"(a3), "r"(b0), "r"(b1));
}

__device__ __forceinline__ uint32_t pack_bf2(float lo, float hi) {
    __nv_bfloat162 v = __floats2bfloat162_rn(lo, hi);   // .x = lo lane
    return *(uint32_t*)&v;
}

__global__ void __launch_bounds__(NT, 2)
sepconv_mma_kernel(const float* __restrict__ x,
                   const float* __restrict__ dwk,    // (3,3,1,96)
                   const float* __restrict__ dwb,    // (96)
                   const float* __restrict__ pwk,    // (1,1,96,96) [ci][co]
                   const float* __restrict__ pwb,    // (96)
                   const float* __restrict__ gamma,
                   const float* __restrict__ beta,
                   const float* __restrict__ mmean,
                   const float* __restrict__ mvar,
                   float* __restrict__ out)
{
    extern __shared__ uint32_t sm[];
    uint32_t* sAhi = sm + O_AHI;
    uint32_t* sAlo = sm + O_ALO;
    uint32_t* sWhi = sm + O_WHI;
    uint32_t* sWlo = sm + O_WLO;
    float* sKw = (float*)(sm + O_KW);
    float* sSc = (float*)(sm + O_SC);
    float* sSh = (float*)(sm + O_SH);
    float* sDb = (float*)(sm + O_DB);

    const int tid = threadIdx.x;
    const int wid = tid >> 5;
    const int l   = tid & 31;
    const int w0  = blockIdx.x * TPX;
    const int h   = blockIdx.y;
    const int b   = blockIdx.z;

    // ---- Phase 0: stage pointwise W (bf16 hi/lo, [co][ci]), dw weights, BN --
    for (int i = tid; i < C_ * (C_ / 2); i += NT) {
        int co = i / (C_ / 2);
        int cw = i - co * (C_ / 2);          // ci word (2 channels)
        float w0f = pwk[(2 * cw) * C_ + co];
        float w1f = pwk[(2 * cw + 1) * C_ + co];
        float h0 = __bfloat162float(__float2bfloat16_rn(w0f));
        float h1 = __bfloat162float(__float2bfloat16_rn(w1f));
        sWhi[co * PW + cw] = pack_bf2(h0, h1);
        sWlo[co * PW + cw] = pack_bf2(w0f - h0, w1f - h1);
    }
    for (int i = tid; i < 9 * C_; i += NT) sKw[i] = dwk[i];
    if (tid < C_) {
        float inv = gamma[tid] * rsqrtf(mvar[tid] + 1e-3f);
        sSc[tid] = inv;
        sSh[tid] = beta[tid] - mmean[tid] * inv + pwb[tid] * inv;
        sDb[tid] = dwb[tid];
    }
    __syncthreads();

    // ---- Phase A: depthwise, flat-coalesced mapping ------------------------
    // warp wid owns pixels [wid*16, wid*16+16); lanes sweep flat float4 index
    // idx = wid*384 + it*32 + l  ->  p = idx/24, q = idx%24.
    // For each neighbor, the 32 lanes read 32 CONSECUTIVE float4s (512B).
    {
        const float4* sKw4 = (const float4*)sKw;
        const float4* sDb4 = (const float4*)sDb;
        const int base_q = wid * 16 * 24;

        #pragma unroll
        for (int it = 0; it < 12; it++) {
            const int idx = base_q + it * 32 + l;
            const int p = idx / 24;              // tile pixel 0..127
            const int q = idx - p * 24;          // channel quad 0..23

            float4 kwr[9];
            #pragma unroll
            for (int nb = 0; nb < 9; nb++) kwr[nb] = sKw4[nb * 24 + q];

            float4 acc = sDb4[q];
            #pragma unroll
            for (int nb = 0; nb < 9; nb++) {
                const int hh = h + nb / 3 - 1;
                const int ww = w0 + p + nb % 3 - 1;
                const bool v = ((unsigned)hh < (unsigned)H_) &&
                               ((unsigned)ww < (unsigned)W_);
                float4 xv = make_float4(0.f, 0.f, 0.f, 0.f);
                if (v)
                    xv = __ldg((const float4*)(x + (((size_t)b * H_ + hh) * W_ + ww) * C_) + q);
                acc.x = fmaf(fmaxf(xv.x, 0.f), kwr[nb].x, acc.x);
                acc.y = fmaf(fmaxf(xv.y, 0.f), kwr[nb].y, acc.y);
                acc.z = fmaf(fmaxf(xv.z, 0.f), kwr[nb].z, acc.z);
                acc.w = fmaf(fmaxf(xv.w, 0.f), kwr[nb].w, acc.w);
            }

            // bf16 hi/lo split, store 2 words each
            float h0 = __bfloat162float(__float2bfloat16_rn(acc.x));
            float h1 = __bfloat162float(__float2bfloat16_rn(acc.y));
            float h2 = __bfloat162float(__float2bfloat16_rn(acc.z));
            float h3 = __bfloat162float(__float2bfloat16_rn(acc.w));
            const int wbase = p * PW + q * 2;
            *(uint2*)(sAhi + wbase) =
                make_uint2(pack_bf2(h0, h1), pack_bf2(h2, h3));
            *(uint2*)(sAlo + wbase) =
                make_uint2(pack_bf2(acc.x - h0, acc.y - h1),
                           pack_bf2(acc.z - h2, acc.w - h3));
        }
    }
    __syncthreads();

    // ---- Phase B: GEMM M=128 N=96 K=96, bf16 split (hi*hi + hi*lo + lo*hi) --
    const int m0 = wid * 16;
    const int g  = l >> 2;
    const int tg = l & 3;

    float d[12][4];
    #pragma unroll
    for (int j = 0; j < 12; j++) {
        d[j][0] = 0.f; d[j][1] = 0.f; d[j][2] = 0.f; d[j][3] = 0.f;
    }

    #pragma unroll
    for (int k = 0; k < 6; k++) {          // k0 = k*16, word base k*8
        const int aw = (m0 + g) * PW + k * 8 + tg;
        const uint32_t ah0 = sAhi[aw];
        const uint32_t ah1 = sAhi[aw + 8 * PW];
        const uint32_t ah2 = sAhi[aw + 4];
        const uint32_t ah3 = sAhi[aw + 8 * PW + 4];
        const uint32_t al0 = sAlo[aw];
        const uint32_t al1 = sAlo[aw + 8 * PW];
        const uint32_t al2 = sAlo[aw + 4];
        const uint32_t al3 = sAlo[aw + 8 * PW + 4];
        #pragma unroll
        for (int j = 0; j < 12; j++) {
            const int bw = (j * 8 + g) * PW + k * 8 + tg;
            const uint32_t bh0 = sWhi[bw];
            const uint32_t bh1 = sWhi[bw + 4];
            const uint32_t bl0 = sWlo[bw];
            const uint32_t bl1 = sWlo[bw + 4];
            mma16816(d[j], ah0, ah1, ah2, ah3, bh0, bh1);
            mma16816(d[j], ah0, ah1, ah2, ah3, bl0, bl1);
            mma16816(d[j], al0, al1, al2, al3, bh0, bh1);
        }
    }

    // ---- Epilogue: BN + store (rows 0..111 only -> warps 0..6) -------------
    if (wid < 7) {
        const int r0 = m0 + g;
        float* base0 = out + (((size_t)b * H_ + h) * W_ + (w0 + r0)) * C_;
        float* base1 = base0 + 8 * (size_t)C_;
        #pragma unroll
        for (int j = 0; j < 12; j++) {
            const int col = j * 8 + tg * 2;
            float2 sc = *(const float2*)(sSc + col);
            float2 sh = *(const float2*)(sSh + col);
            float2 r;
            r.x = fmaf(d[j][0], sc.x, sh.x);
            r.y = fmaf(d[j][1], sc.y, sh.y);
            *(float2*)(base0 + col) = r;
            r.x = fmaf(d[j][2], sc.x, sh.x);
            r.y = fmaf(d[j][3], sc.y, sh.y);
            *(float2*)(base1 + col) = r;
        }
    }
}

extern "C" void kernel_launch(void* const* d_in, const int* in_sizes, int n_in,
                              void* d_out, int out_size)
{
    (void)in_sizes; (void)n_in; (void)out_size;
    const float* x     = (const float*)d_in[0];
    const float* dwk   = (const float*)d_in[1];
    const float* dwb   = (const float*)d_in[2];
    const float* pwk   = (const float*)d_in[3];
    const float* pwb   = (const float*)d_in[4];
    const float* gamma = (const float*)d_in[5];
    const float* beta  = (const float*)d_in[6];
    const float* mmean = (const float*)d_in[7];
    const float* mvar  = (const float*)d_in[8];
    float* out = (float*)d_out;

    cudaFuncSetAttribute(sepconv_mma_kernel,
                         cudaFuncAttributeMaxDynamicSharedMemorySize, SMEM_BYTES);

    dim3 grid(W_ / TPX, H_, B_);           // (2, 224, 16)
    sepconv_mma_kernel<<<grid, NT, SMEM_BYTES>>>(
        x, dwk, dwb, pwk, pwb, gamma, beta, mmean, mvar, out);
}